// round 13
// baseline (speedup 1.0000x reference)
#include <cuda_runtime.h>
#include <cuda_fp16.h>
#include <mma.h>
#include <cstdint>

using namespace nvcuda;

#define N_NODES 50000
#define C_IN 32
#define HID 64
#define ELLW 96
#define NB 64                 // nodes per block in layer kernels
#define FULL 0xffffffffu

// Scratch (allocation-free rule: __device__ globals)
__device__ int     g_cnt[N_NODES];
__device__ int     g_ell[N_NODES * ELLW];    // 19.2 MB neighbor lists
__device__ __half2 g_h016[N_NODES * 32];     // half2-packed h0: 64ch = 128B/row
__device__ __half2 g_x16[N_NODES * 16];      // half2-packed x: 32ch = 64B/row

// ---------------------------------------------------------------------------
// Launch 1: zero counters + build fp16 copy of x
__global__ void k_prep(const float2* __restrict__ x2) {
    int i = blockIdx.x * blockDim.x + threadIdx.x;
    int stride = gridDim.x * blockDim.x;
    for (int j = i; j < N_NODES; j += stride) g_cnt[j] = 0;
    for (int j = i; j < N_NODES * 16; j += stride) {
        float2 v = x2[j];
        g_x16[j] = __floats2half2_rn(v.x, v.y);
    }
}

// Launch 2: ELL fill (atomic cursor per destination node)
__global__ void k_ellfill(const int* __restrict__ ei, int E) {
    int e = blockIdx.x * blockDim.x + threadIdx.x;
    if (e >= E) return;
    int src = ei[e];
    int dst = ei[E + e];
    int pos = atomicAdd(g_cnt + dst, 1);
    if (pos < ELLW) g_ell[dst * ELLW + pos] = src;
}

// ---------------------------------------------------------------------------
// Launch 3: Layer 0. Block = 64 nodes, 256 threads (8 warps).
// Phase A: PAIRED gather (2 nodes/warp/round, 2x MLP) -> fp16 act.
// Phase B: wmma GEMM 64x64x64.  Phase C: bias+normalize+relu -> g_h016.
#define L0_ALD 72     // act ld (halves)
#define L0_CLD 68     // C ld (floats)
__global__ void __launch_bounds__(256, 6) k_layer0(
        const float* __restrict__ Wl0,
        const float* __restrict__ b0,
        const float* __restrict__ Wr0) {
    __shared__ alignas(16) char uAC[NB * L0_CLD * 4];   // act fp16 then C fp32
    __shared__ alignas(16) __half sW[64 * L0_ALD];
    __shared__ float sb[HID];

    __half* Act = reinterpret_cast<__half*>(uAC);
    float*  Cm  = reinterpret_cast<float*>(uAC);

    int tid  = threadIdx.x;
    int warp = tid >> 5;
    int lane = tid & 31;

    for (int j = tid; j < 64 * HID; j += 256) {
        int kk = j >> 6, o = j & 63;
        float w = (kk < 32) ? Wl0[kk * HID + o] : Wr0[(kk - 32) * HID + o];
        sW[kk * L0_ALD + o] = __float2half(w);
    }
    if (tid < HID) sb[tid] = b0[tid];
    __syncthreads();

    // ---- Phase A: paired gather (4 rounds, 2 nodes per warp) ----
    int g = lane >> 4;      // neighbor sub-group (0,1)
    int c = lane & 15;      // half2 index within 32-ch row
#pragma unroll 1
    for (int r = 0; r < 4; r++) {
        int nA = r * 8 + warp;            // 0..31
        int nB = nA + 32;                 // 32..63
        int nodeA = blockIdx.x * NB + nA;
        int nodeB = blockIdx.x * NB + nB;
        bool vA = nodeA < N_NODES, vB = nodeB < N_NODES;
        int degA = vA ? g_cnt[nodeA] : 0;
        int degB = vB ? g_cnt[nodeB] : 0;
        int dLA = min(degA, ELLW), dLB = min(degB, ELLW);
        int rowA = nodeA * ELLW, rowB = nodeB * ELLW;
        float axA = 0.f, ayA = 0.f, axB = 0.f, ayB = 0.f;
        int dM = max(dLA, dLB);
        for (int base = 0; base < dM; base += 32) {
            int nbA = vA ? g_ell[rowA + max(min(base + lane, dLA - 1), 0)] : 0;
            int nbB = vB ? g_ell[rowB + max(min(base + lane, dLB - 1), 0)] : 0;
            int mA = dLA - base, mB = dLB - base;
#pragma unroll
            for (int i = 0; i < 32; i += 2) {
                int sA = __shfl_sync(FULL, nbA, i + g);
                int sB = __shfl_sync(FULL, nbB, i + g);
                float2 fA = __half22float2(g_x16[sA * 16 + c]);
                float2 fB = __half22float2(g_x16[sB * 16 + c]);
                if (i + g < mA) { axA += fA.x; ayA += fA.y; }
                if (i + g < mB) { axB += fB.x; ayB += fB.y; }
            }
        }
        axA += __shfl_xor_sync(FULL, axA, 16);
        ayA += __shfl_xor_sync(FULL, ayA, 16);
        axB += __shfl_xor_sync(FULL, axB, 16);
        ayB += __shfl_xor_sync(FULL, ayB, 16);
        if (vA) {
            float ic = 1.0f / fmaxf((float)degA, 1.0f);
            __half2* arow = reinterpret_cast<__half2*>(Act + nA * L0_ALD);
            if (lane < 16) arow[c] = __floats2half2_rn(axA * ic, ayA * ic);
            else           arow[16 + c] = g_x16[nodeA * 16 + c];
        }
        if (vB) {
            float ic = 1.0f / fmaxf((float)degB, 1.0f);
            __half2* arow = reinterpret_cast<__half2*>(Act + nB * L0_ALD);
            if (lane < 16) arow[c] = __floats2half2_rn(axB * ic, ayB * ic);
            else           arow[16 + c] = g_x16[nodeB * 16 + c];
        }
    }
    __syncthreads();

    // ---- Phase B: wmma GEMM 64x64x64 ----
    {
        int mi = warp & 3;
        int nj = warp >> 2;
        wmma::fragment<wmma::accumulator, 16, 16, 16, float> c0, c1;
        wmma::fill_fragment(c0, 0.0f);
        wmma::fill_fragment(c1, 0.0f);
#pragma unroll
        for (int k = 0; k < 4; k++) {
            wmma::fragment<wmma::matrix_a, 16, 16, 16, __half, wmma::row_major> a;
            wmma::fragment<wmma::matrix_b, 16, 16, 16, __half, wmma::row_major> b0f, b1f;
            wmma::load_matrix_sync(a, Act + (mi * 16) * L0_ALD + k * 16, L0_ALD);
            wmma::load_matrix_sync(b0f, sW + (k * 16) * L0_ALD + nj * 16, L0_ALD);
            wmma::load_matrix_sync(b1f, sW + (k * 16) * L0_ALD + (nj + 2) * 16, L0_ALD);
            wmma::mma_sync(c0, a, b0f, c0);
            wmma::mma_sync(c1, a, b1f, c1);
        }
        __syncthreads();
        wmma::store_matrix_sync(Cm + (mi * 16) * L0_CLD + nj * 16, c0, L0_CLD, wmma::mem_row_major);
        wmma::store_matrix_sync(Cm + (mi * 16) * L0_CLD + (nj + 2) * 16, c1, L0_CLD, wmma::mem_row_major);
    }
    __syncthreads();

    // ---- Phase C: bias + normalize + relu -> g_h016 ----
#pragma unroll 1
    for (int r = 0; r < 8; r++) {
        int n = r * 8 + warp;
        int node = blockIdx.x * NB + n;
        if (node >= N_NODES) continue;
        float a0 = Cm[n * L0_CLD + lane]      + sb[lane];
        float a1 = Cm[n * L0_CLD + lane + 32] + sb[lane + 32];
        float ss = a0 * a0 + a1 * a1;
#pragma unroll
        for (int off = 16; off > 0; off >>= 1)
            ss += __shfl_xor_sync(FULL, ss, off);
        float inv = 1.0f / fmaxf(sqrtf(ss), 1e-12f);
        float o0 = fmaxf(a0 * inv, 0.0f);
        float o1 = fmaxf(a1 * inv, 0.0f);
        int src_lo = (2 * lane) & 31, src_hi = (2 * lane + 1) & 31;
        float lo0 = __shfl_sync(FULL, o0, src_lo);
        float lo1 = __shfl_sync(FULL, o1, src_lo);
        float hi0 = __shfl_sync(FULL, o0, src_hi);
        float hi1 = __shfl_sync(FULL, o1, src_hi);
        float lo = (lane < 16) ? lo0 : lo1;
        float hi = (lane < 16) ? hi0 : hi1;
        g_h016[node * 32 + lane] = __floats2half2_rn(lo, hi);
    }
}

// ---------------------------------------------------------------------------
// Launch 4: Layer 1 + classifier. Block = 64 nodes, 256 threads.
// Phase A: PAIRED gather (2 nodes/warp/round). Phase B: wmma 64x64x128.
// Phase C: bias+normalize -> h1 fp16. Phase D: wmma 64x32x64. Phase E: out.
#define L1_ALD 136    // act ld (halves)
#define L1_WLD 72     // weight ld
#define L1_CLD 68     // C ld (floats)
#define H1_LD  72     // h1 ld (halves)
#define C2_LD  36     // C2 ld (floats)
#define WC_LD  40     // Wc1 ld (halves)
__global__ void __launch_bounds__(256, 5) k_layer1(
        const float* __restrict__ Wl1,
        const float* __restrict__ b1,
        const float* __restrict__ Wr1,
        const float* __restrict__ Wc1,
        const float* __restrict__ bc1,
        const float* __restrict__ Wc2,
        const float* __restrict__ bc2,
        float* __restrict__ out) {
    __shared__ alignas(16) char uAC[NB * L1_ALD * 2];          // act fp16 == C fp32
    __shared__ alignas(16) char uW[128 * L1_WLD * 2];          // W fp16 -> H1 fp16 | C2 fp32
    __shared__ alignas(16) __half sWc1h[64 * WC_LD];
    __shared__ float sb[HID];
    __shared__ float sbc1[32];
    __shared__ float sWc2s[32];

    __half* Act = reinterpret_cast<__half*>(uAC);
    float*  Cm  = reinterpret_cast<float*>(uAC);
    __half* W   = reinterpret_cast<__half*>(uW);
    __half* H1  = reinterpret_cast<__half*>(uW);               // 9216B
    float*  C2  = reinterpret_cast<float*>(uW + 9216);         // 9216B

    int tid  = threadIdx.x;
    int warp = tid >> 5;
    int lane = tid & 31;

    for (int j = tid; j < 128 * HID; j += 256) {
        int kk = j >> 6, o = j & 63;
        float w = (kk < 64) ? Wl1[kk * HID + o] : Wr1[(kk - 64) * HID + o];
        W[kk * L1_WLD + o] = __float2half(w);
    }
    for (int j = tid; j < 64 * 32; j += 256) {
        int kk = j >> 5, o = j & 31;
        sWc1h[kk * WC_LD + o] = __float2half(Wc1[kk * 32 + o]);
    }
    if (tid < HID) sb[tid] = b1[tid];
    if (tid < 32) { sbc1[tid] = bc1[tid]; sWc2s[tid] = Wc2[tid]; }
    __syncthreads();

    // ---- Phase A: paired gather (4 rounds, 2 nodes per warp) ----
#pragma unroll 1
    for (int r = 0; r < 4; r++) {
        int nA = r * 8 + warp;            // 0..31
        int nB = nA + 32;                 // 32..63
        int nodeA = blockIdx.x * NB + nA;
        int nodeB = blockIdx.x * NB + nB;
        bool vA = nodeA < N_NODES, vB = nodeB < N_NODES;
        int degA = vA ? g_cnt[nodeA] : 0;
        int degB = vB ? g_cnt[nodeB] : 0;
        int dLA = min(degA, ELLW), dLB = min(degB, ELLW);
        int rowA = nodeA * ELLW, rowB = nodeB * ELLW;
        float axA = 0.f, ayA = 0.f, axB = 0.f, ayB = 0.f;
        int dM = max(dLA, dLB);
        for (int base = 0; base < dM; base += 32) {
            int nbA = vA ? g_ell[rowA + max(min(base + lane, dLA - 1), 0)] : 0;
            int nbB = vB ? g_ell[rowB + max(min(base + lane, dLB - 1), 0)] : 0;
            int mA = dLA - base, mB = dLB - base;
#pragma unroll
            for (int i = 0; i < 32; i++) {
                int sA = __shfl_sync(FULL, nbA, i);
                int sB = __shfl_sync(FULL, nbB, i);
                float2 fA = __half22float2(g_h016[sA * 32 + lane]);
                float2 fB = __half22float2(g_h016[sB * 32 + lane]);
                if (i < mA) { axA += fA.x; ayA += fA.y; }
                if (i < mB) { axB += fB.x; ayB += fB.y; }
            }
        }
        if (vA) {
            float ic = 1.0f / fmaxf((float)degA, 1.0f);
            __half2* arow = reinterpret_cast<__half2*>(Act + nA * L1_ALD);
            arow[lane]      = __floats2half2_rn(axA * ic, ayA * ic);
            arow[32 + lane] = g_h016[nodeA * 32 + lane];
        }
        if (vB) {
            float ic = 1.0f / fmaxf((float)degB, 1.0f);
            __half2* arow = reinterpret_cast<__half2*>(Act + nB * L1_ALD);
            arow[lane]      = __floats2half2_rn(axB * ic, ayB * ic);
            arow[32 + lane] = g_h016[nodeB * 32 + lane];
        }
    }
    __syncthreads();

    // ---- Phase B: wmma GEMM 64x64x128 ----
    {
        int mi = warp & 3;
        int nj = warp >> 2;
        wmma::fragment<wmma::accumulator, 16, 16, 16, float> c0, c1;
        wmma::fill_fragment(c0, 0.0f);
        wmma::fill_fragment(c1, 0.0f);
#pragma unroll
        for (int k = 0; k < 8; k++) {
            wmma::fragment<wmma::matrix_a, 16, 16, 16, __half, wmma::row_major> a;
            wmma::fragment<wmma::matrix_b, 16, 16, 16, __half, wmma::row_major> b0f, b1f;
            wmma::load_matrix_sync(a, Act + (mi * 16) * L1_ALD + k * 16, L1_ALD);
            wmma::load_matrix_sync(b0f, W + (k * 16) * L1_WLD + nj * 16, L1_WLD);
            wmma::load_matrix_sync(b1f, W + (k * 16) * L1_WLD + (nj + 2) * 16, L1_WLD);
            wmma::mma_sync(c0, a, b0f, c0);
            wmma::mma_sync(c1, a, b1f, c1);
        }
        __syncthreads();
        wmma::store_matrix_sync(Cm + (mi * 16) * L1_CLD + nj * 16, c0, L1_CLD, wmma::mem_row_major);
        wmma::store_matrix_sync(Cm + (mi * 16) * L1_CLD + (nj + 2) * 16, c1, L1_CLD, wmma::mem_row_major);
    }
    __syncthreads();

    // ---- Phase C: bias + normalize -> H1 fp16 (overwrites W region) ----
#pragma unroll 1
    for (int r = 0; r < 8; r++) {
        int n = r * 8 + warp;
        float a0 = Cm[n * L1_CLD + lane]      + sb[lane];
        float a1 = Cm[n * L1_CLD + lane + 32] + sb[lane + 32];
        float ss = a0 * a0 + a1 * a1;
#pragma unroll
        for (int off = 16; off > 0; off >>= 1)
            ss += __shfl_xor_sync(FULL, ss, off);
        float inv = 1.0f / fmaxf(sqrtf(ss), 1e-12f);
        H1[n * H1_LD + lane]      = __float2half(a0 * inv);
        H1[n * H1_LD + lane + 32] = __float2half(a1 * inv);
    }
    __syncthreads();

    // ---- Phase D: wmma GEMM 64x32x64 (h1 @ Wc1) ----
    {
        int mi = warp & 3;
        int nj = warp >> 2;
        wmma::fragment<wmma::accumulator, 16, 16, 16, float> cf;
        wmma::fill_fragment(cf, 0.0f);
#pragma unroll
        for (int k = 0; k < 4; k++) {
            wmma::fragment<wmma::matrix_a, 16, 16, 16, __half, wmma::row_major> a;
            wmma::fragment<wmma::matrix_b, 16, 16, 16, __half, wmma::row_major> bf;
            wmma::load_matrix_sync(a, H1 + (mi * 16) * H1_LD + k * 16, H1_LD);
            wmma::load_matrix_sync(bf, sWc1h + (k * 16) * WC_LD + nj * 16, WC_LD);
            wmma::mma_sync(cf, a, bf, cf);
        }
        wmma::store_matrix_sync(C2 + (mi * 16) * C2_LD + nj * 16, cf, C2_LD, wmma::mem_row_major);
    }
    __syncthreads();

    // ---- Phase E: bias + relu + dot(Wc2) -> out ----
#pragma unroll 1
    for (int r = 0; r < 8; r++) {
        int n = r * 8 + warp;
        int node = blockIdx.x * NB + n;
        if (node >= N_NODES) continue;
        float v = C2[n * C2_LD + lane] + sbc1[lane];
        v = fmaxf(v, 0.0f);
        float p = v * sWc2s[lane];
#pragma unroll
        for (int off = 16; off > 0; off >>= 1)
            p += __shfl_xor_sync(FULL, p, off);
        if (lane == 0) out[node] = p + bc2[0];
    }
}

// ---------------------------------------------------------------------------
extern "C" void kernel_launch(void* const* d_in, const int* in_sizes, int n_in,
                              void* d_out, int out_size) {
    const float* x    = (const float*)d_in[0];
    const int*   ei   = (const int*)d_in[1];     // int32 edge index
    const float* Wl0  = (const float*)d_in[2];
    const float* b0   = (const float*)d_in[3];
    const float* Wr0  = (const float*)d_in[4];
    const float* Wl1  = (const float*)d_in[5];
    const float* b1   = (const float*)d_in[6];
    const float* Wr1  = (const float*)d_in[7];
    const float* Wc1  = (const float*)d_in[8];
    const float* bc1  = (const float*)d_in[9];
    const float* Wc2  = (const float*)d_in[10];
    const float* bc2  = (const float*)d_in[11];
    float* out = (float*)d_out;

    int E = in_sizes[1] / 2;   // 1,600,000
    int nblk = (N_NODES + NB - 1) / NB;

    k_prep<<<512, 256>>>((const float2*)x);
    k_ellfill<<<(E + 255) / 256, 256>>>(ei, E);
    k_layer0<<<nblk, 256>>>(Wl0, b0, Wr0);
    k_layer1<<<nblk, 256>>>(Wl1, b1, Wr1, Wc1, bc1, Wc2, bc2, out);
}

// round 15
// speedup vs baseline: 1.0849x; 1.0849x over previous
#include <cuda_runtime.h>
#include <cuda_fp16.h>
#include <mma.h>
#include <cstdint>

using namespace nvcuda;

#define N_NODES 50000
#define C_IN 32
#define HID 64
#define ELLW 96
#define NB 64                 // nodes per block in layer kernels
#define FULL 0xffffffffu
#define SENT N_NODES          // sentinel node: zero feature row

// Scratch (allocation-free rule: __device__ globals)
__device__ int     g_cnt[N_NODES];
__device__ int     g_ell[N_NODES * ELLW];         // sentinel-padded neighbor lists
__device__ __half2 g_h016[(N_NODES + 1) * 32];    // half2 h0 rows (+ zero sentinel row)
__device__ __half2 g_x16[(N_NODES + 1) * 16];     // half2 x rows (+ zero sentinel row)

// ---------------------------------------------------------------------------
// Launch 1: counters=0, ELL=sentinel, fp16 x copy, zero sentinel rows
__global__ void k_prep(const float2* __restrict__ x2) {
    int i = blockIdx.x * blockDim.x + threadIdx.x;
    int stride = gridDim.x * blockDim.x;
    for (int j = i; j < N_NODES * ELLW; j += stride) g_ell[j] = SENT;
    for (int j = i; j < N_NODES; j += stride) g_cnt[j] = 0;
    for (int j = i; j < N_NODES * 16; j += stride) {
        float2 v = x2[j];
        g_x16[j] = __floats2half2_rn(v.x, v.y);
    }
    if (i < 16) g_x16[N_NODES * 16 + i] = __floats2half2_rn(0.f, 0.f);
    if (i < 32) g_h016[N_NODES * 32 + i] = __floats2half2_rn(0.f, 0.f);
}

// Launch 2: ELL fill (atomic cursor per destination node)
__global__ void k_ellfill(const int* __restrict__ ei, int E) {
    int e = blockIdx.x * blockDim.x + threadIdx.x;
    if (e >= E) return;
    int src = ei[e];
    int dst = ei[E + e];
    int pos = atomicAdd(g_cnt + dst, 1);
    if (pos < ELLW) g_ell[dst * ELLW + pos] = src;
}

// ---------------------------------------------------------------------------
// Launch 3: Layer 0. Block = 64 nodes, 256 threads (8 warps).
// Phase A: branchless sentinel-padded gather, HADD2-paired -> fp16 act.
// Phase B: wmma GEMM 64x64x64.  Phase C: bias+normalize+relu -> g_h016.
#define L0_ALD 72     // act ld (halves)
#define L0_CLD 68     // C ld (floats)
__global__ void __launch_bounds__(256, 6) k_layer0(
        const float* __restrict__ Wl0,
        const float* __restrict__ b0,
        const float* __restrict__ Wr0) {
    __shared__ alignas(16) char uAC[NB * L0_CLD * 4];   // act fp16 then C fp32
    __shared__ alignas(16) __half sW[64 * L0_ALD];
    __shared__ float sb[HID];

    __half* Act = reinterpret_cast<__half*>(uAC);
    float*  Cm  = reinterpret_cast<float*>(uAC);

    int tid  = threadIdx.x;
    int warp = tid >> 5;
    int lane = tid & 31;

    for (int j = tid; j < 64 * HID; j += 256) {
        int kk = j >> 6, o = j & 63;
        float w = (kk < 32) ? Wl0[kk * HID + o] : Wr0[(kk - 32) * HID + o];
        sW[kk * L0_ALD + o] = __float2half(w);
    }
    if (tid < HID) sb[tid] = b0[tid];
    __syncthreads();

    // ---- Phase A: gather (8 rounds, warp per node) ----
    int g = lane >> 4;      // half-warp id (0,1)
    int c = lane & 15;      // half2 index within 32-ch row
#pragma unroll 1
    for (int r = 0; r < 8; r++) {
        int n = r * 8 + warp;
        int node = blockIdx.x * NB + n;
        if (node < N_NODES) {
            int deg  = g_cnt[node];
            int degP = (min(deg, ELLW) + 31) & ~31;   // sentinel-padded
            int row  = node * ELLW;
            float ax = 0.f, ay = 0.f;
            for (int base = 0; base < degP; base += 32) {
                int nb = g_ell[row + base + lane];    // sentinel beyond deg
#pragma unroll
                for (int i = 0; i < 32; i += 4) {     // half-warp: neighbors i+g, i+2+g
                    int s0 = __shfl_sync(FULL, nb, i + g);
                    int s1 = __shfl_sync(FULL, nb, i + 2 + g);
                    __half2 h = __hadd2(g_x16[s0 * 16 + c], g_x16[s1 * 16 + c]);
                    float2 f = __half22float2(h);
                    ax += f.x; ay += f.y;
                }
            }
            ax += __shfl_xor_sync(FULL, ax, 16);
            ay += __shfl_xor_sync(FULL, ay, 16);
            float ic = 1.0f / fmaxf((float)deg, 1.0f);
            __half2* arow = reinterpret_cast<__half2*>(Act + n * L0_ALD);
            if (lane < 16) arow[c] = __floats2half2_rn(ax * ic, ay * ic);   // mean ch{2c,2c+1}
            else           arow[16 + c] = g_x16[node * 16 + c];             // self
        }
    }
    __syncthreads();

    // ---- Phase B: wmma GEMM 64x64x64 ----
    {
        int mi = warp & 3;
        int nj = warp >> 2;
        wmma::fragment<wmma::accumulator, 16, 16, 16, float> c0, c1;
        wmma::fill_fragment(c0, 0.0f);
        wmma::fill_fragment(c1, 0.0f);
#pragma unroll
        for (int k = 0; k < 4; k++) {
            wmma::fragment<wmma::matrix_a, 16, 16, 16, __half, wmma::row_major> a;
            wmma::fragment<wmma::matrix_b, 16, 16, 16, __half, wmma::row_major> b0f, b1f;
            wmma::load_matrix_sync(a, Act + (mi * 16) * L0_ALD + k * 16, L0_ALD);
            wmma::load_matrix_sync(b0f, sW + (k * 16) * L0_ALD + nj * 16, L0_ALD);
            wmma::load_matrix_sync(b1f, sW + (k * 16) * L0_ALD + (nj + 2) * 16, L0_ALD);
            wmma::mma_sync(c0, a, b0f, c0);
            wmma::mma_sync(c1, a, b1f, c1);
        }
        __syncthreads();
        wmma::store_matrix_sync(Cm + (mi * 16) * L0_CLD + nj * 16, c0, L0_CLD, wmma::mem_row_major);
        wmma::store_matrix_sync(Cm + (mi * 16) * L0_CLD + (nj + 2) * 16, c1, L0_CLD, wmma::mem_row_major);
    }
    __syncthreads();

    // ---- Phase C: bias + normalize + relu -> g_h016 ----
#pragma unroll 1
    for (int r = 0; r < 8; r++) {
        int n = r * 8 + warp;
        int node = blockIdx.x * NB + n;
        if (node >= N_NODES) continue;
        float a0 = Cm[n * L0_CLD + lane]      + sb[lane];
        float a1 = Cm[n * L0_CLD + lane + 32] + sb[lane + 32];
        float ss = a0 * a0 + a1 * a1;
#pragma unroll
        for (int off = 16; off > 0; off >>= 1)
            ss += __shfl_xor_sync(FULL, ss, off);
        float inv = 1.0f / fmaxf(sqrtf(ss), 1e-12f);
        float o0 = fmaxf(a0 * inv, 0.0f);
        float o1 = fmaxf(a1 * inv, 0.0f);
        int src_lo = (2 * lane) & 31, src_hi = (2 * lane + 1) & 31;
        float lo0 = __shfl_sync(FULL, o0, src_lo);
        float lo1 = __shfl_sync(FULL, o1, src_lo);
        float hi0 = __shfl_sync(FULL, o0, src_hi);
        float hi1 = __shfl_sync(FULL, o1, src_hi);
        float lo = (lane < 16) ? lo0 : lo1;
        float hi = (lane < 16) ? hi0 : hi1;
        g_h016[node * 32 + lane] = __floats2half2_rn(lo, hi);
    }
}

// ---------------------------------------------------------------------------
// Launch 4: Layer 1 + classifier. Block = 64 nodes, 256 threads.
// Phase A: branchless sentinel-padded gather, HADD2-paired.
// Phase B: wmma 64x64x128. Phase C: bias+normalize -> h1 fp16.
// Phase D: wmma 64x32x64. Phase E: bias+relu+dot -> out.
#define L1_ALD 136    // act ld (halves)
#define L1_WLD 72     // weight ld
#define L1_CLD 68     // C ld (floats)
#define H1_LD  72     // h1 ld (halves)
#define C2_LD  36     // C2 ld (floats)
#define WC_LD  40     // Wc1 ld (halves)
__global__ void __launch_bounds__(256, 5) k_layer1(
        const float* __restrict__ Wl1,
        const float* __restrict__ b1,
        const float* __restrict__ Wr1,
        const float* __restrict__ Wc1,
        const float* __restrict__ bc1,
        const float* __restrict__ Wc2,
        const float* __restrict__ bc2,
        float* __restrict__ out) {
    __shared__ alignas(16) char uAC[NB * L1_ALD * 2];          // act fp16 == C fp32
    __shared__ alignas(16) char uW[128 * L1_WLD * 2];          // W fp16 -> H1 fp16 | C2 fp32
    __shared__ alignas(16) __half sWc1h[64 * WC_LD];
    __shared__ float sb[HID];
    __shared__ float sbc1[32];
    __shared__ float sWc2s[32];

    __half* Act = reinterpret_cast<__half*>(uAC);
    float*  Cm  = reinterpret_cast<float*>(uAC);
    __half* W   = reinterpret_cast<__half*>(uW);
    __half* H1  = reinterpret_cast<__half*>(uW);               // 9216B
    float*  C2  = reinterpret_cast<float*>(uW + 9216);         // 9216B

    int tid  = threadIdx.x;
    int warp = tid >> 5;
    int lane = tid & 31;

    for (int j = tid; j < 128 * HID; j += 256) {
        int kk = j >> 6, o = j & 63;
        float w = (kk < 64) ? Wl1[kk * HID + o] : Wr1[(kk - 64) * HID + o];
        W[kk * L1_WLD + o] = __float2half(w);
    }
    for (int j = tid; j < 64 * 32; j += 256) {
        int kk = j >> 5, o = j & 31;
        sWc1h[kk * WC_LD + o] = __float2half(Wc1[kk * 32 + o]);
    }
    if (tid < HID) sb[tid] = b1[tid];
    if (tid < 32) { sbc1[tid] = bc1[tid]; sWc2s[tid] = Wc2[tid]; }
    __syncthreads();

    // ---- Phase A: gather (8 rounds, warp per node) ----
#pragma unroll 1
    for (int r = 0; r < 8; r++) {
        int n = r * 8 + warp;
        int node = blockIdx.x * NB + n;
        if (node < N_NODES) {
            int deg  = g_cnt[node];
            int degP = (min(deg, ELLW) + 31) & ~31;
            int row  = node * ELLW;
            float ax = 0.f, ay = 0.f;   // ch {2*lane, 2*lane+1}
            for (int base = 0; base < degP; base += 32) {
                int nb = g_ell[row + base + lane];   // sentinel beyond deg
#pragma unroll
                for (int i = 0; i < 32; i += 2) {
                    int s0 = __shfl_sync(FULL, nb, i);
                    int s1 = __shfl_sync(FULL, nb, i + 1);
                    __half2 h = __hadd2(g_h016[s0 * 32 + lane], g_h016[s1 * 32 + lane]);
                    float2 f = __half22float2(h);
                    ax += f.x; ay += f.y;
                }
            }
            float ic = 1.0f / fmaxf((float)deg, 1.0f);
            __half2* arow = reinterpret_cast<__half2*>(Act + n * L1_ALD);
            arow[lane]      = __floats2half2_rn(ax * ic, ay * ic);   // mean ch{2l,2l+1}
            arow[32 + lane] = g_h016[node * 32 + lane];              // self
        }
    }
    __syncthreads();

    // ---- Phase B: wmma GEMM 64x64x128 ----
    {
        int mi = warp & 3;
        int nj = warp >> 2;
        wmma::fragment<wmma::accumulator, 16, 16, 16, float> c0, c1;
        wmma::fill_fragment(c0, 0.0f);
        wmma::fill_fragment(c1, 0.0f);
#pragma unroll
        for (int k = 0; k < 8; k++) {
            wmma::fragment<wmma::matrix_a, 16, 16, 16, __half, wmma::row_major> a;
            wmma::fragment<wmma::matrix_b, 16, 16, 16, __half, wmma::row_major> b0f, b1f;
            wmma::load_matrix_sync(a, Act + (mi * 16) * L1_ALD + k * 16, L1_ALD);
            wmma::load_matrix_sync(b0f, W + (k * 16) * L1_WLD + nj * 16, L1_WLD);
            wmma::load_matrix_sync(b1f, W + (k * 16) * L1_WLD + (nj + 2) * 16, L1_WLD);
            wmma::mma_sync(c0, a, b0f, c0);
            wmma::mma_sync(c1, a, b1f, c1);
        }
        __syncthreads();
        wmma::store_matrix_sync(Cm + (mi * 16) * L1_CLD + nj * 16, c0, L1_CLD, wmma::mem_row_major);
        wmma::store_matrix_sync(Cm + (mi * 16) * L1_CLD + (nj + 2) * 16, c1, L1_CLD, wmma::mem_row_major);
    }
    __syncthreads();

    // ---- Phase C: bias + normalize -> H1 fp16 (overwrites W region) ----
#pragma unroll 1
    for (int r = 0; r < 8; r++) {
        int n = r * 8 + warp;
        float a0 = Cm[n * L1_CLD + lane]      + sb[lane];
        float a1 = Cm[n * L1_CLD + lane + 32] + sb[lane + 32];
        float ss = a0 * a0 + a1 * a1;
#pragma unroll
        for (int off = 16; off > 0; off >>= 1)
            ss += __shfl_xor_sync(FULL, ss, off);
        float inv = 1.0f / fmaxf(sqrtf(ss), 1e-12f);
        H1[n * H1_LD + lane]      = __float2half(a0 * inv);
        H1[n * H1_LD + lane + 32] = __float2half(a1 * inv);
    }
    __syncthreads();

    // ---- Phase D: wmma GEMM 64x32x64 (h1 @ Wc1) ----
    {
        int mi = warp & 3;
        int nj = warp >> 2;
        wmma::fragment<wmma::accumulator, 16, 16, 16, float> cf;
        wmma::fill_fragment(cf, 0.0f);
#pragma unroll
        for (int k = 0; k < 4; k++) {
            wmma::fragment<wmma::matrix_a, 16, 16, 16, __half, wmma::row_major> a;
            wmma::fragment<wmma::matrix_b, 16, 16, 16, __half, wmma::row_major> bf;
            wmma::load_matrix_sync(a, H1 + (mi * 16) * H1_LD + k * 16, H1_LD);
            wmma::load_matrix_sync(bf, sWc1h + (k * 16) * WC_LD + nj * 16, WC_LD);
            wmma::mma_sync(cf, a, bf, cf);
        }
        wmma::store_matrix_sync(C2 + (mi * 16) * C2_LD + nj * 16, cf, C2_LD, wmma::mem_row_major);
    }
    __syncthreads();

    // ---- Phase E: bias + relu + dot(Wc2) -> out ----
#pragma unroll 1
    for (int r = 0; r < 8; r++) {
        int n = r * 8 + warp;
        int node = blockIdx.x * NB + n;
        if (node >= N_NODES) continue;
        float v = C2[n * C2_LD + lane] + sbc1[lane];
        v = fmaxf(v, 0.0f);
        float p = v * sWc2s[lane];
#pragma unroll
        for (int off = 16; off > 0; off >>= 1)
            p += __shfl_xor_sync(FULL, p, off);
        if (lane == 0) out[node] = p + bc2[0];
    }
}

// ---------------------------------------------------------------------------
extern "C" void kernel_launch(void* const* d_in, const int* in_sizes, int n_in,
                              void* d_out, int out_size) {
    const float* x    = (const float*)d_in[0];
    const int*   ei   = (const int*)d_in[1];     // int32 edge index
    const float* Wl0  = (const float*)d_in[2];
    const float* b0   = (const float*)d_in[3];
    const float* Wr0  = (const float*)d_in[4];
    const float* Wl1  = (const float*)d_in[5];
    const float* b1   = (const float*)d_in[6];
    const float* Wr1  = (const float*)d_in[7];
    const float* Wc1  = (const float*)d_in[8];
    const float* bc1  = (const float*)d_in[9];
    const float* Wc2  = (const float*)d_in[10];
    const float* bc2  = (const float*)d_in[11];
    float* out = (float*)d_out;

    int E = in_sizes[1] / 2;   // 1,600,000
    int nblk = (N_NODES + NB - 1) / NB;

    k_prep<<<1024, 256>>>((const float2*)x);
    k_ellfill<<<(E + 255) / 256, 256>>>(ei, E);
    k_layer0<<<nblk, 256>>>(Wl0, b0, Wr0);
    k_layer1<<<nblk, 256>>>(Wl1, b1, Wr1, Wc1, bc1, Wc2, bc2, out);
}

// round 17
// speedup vs baseline: 1.1603x; 1.0694x over previous
#include <cuda_runtime.h>
#include <cuda_fp16.h>
#include <mma.h>
#include <cstdint>

using namespace nvcuda;

#define N_NODES 50000
#define C_IN 32
#define HID 64
#define ELLW 96
#define NB 32                 // nodes per block in layer kernels
#define FULL 0xffffffffu
#define SENT N_NODES          // sentinel node: zero feature row

// Scratch (allocation-free rule: __device__ globals)
__device__ int     g_cnt[N_NODES];
__device__ int     g_ell[N_NODES * ELLW];         // sentinel-padded neighbor lists
__device__ __half2 g_h016[(N_NODES + 1) * 32];    // half2 h0 rows (+ zero sentinel row)
__device__ __half2 g_x16[(N_NODES + 1) * 16];     // half2 x rows (+ zero sentinel row)

// ---------------------------------------------------------------------------
// Launch 1: counters=0, ELL=sentinel, fp16 x copy, zero sentinel rows
__global__ void k_prep(const float2* __restrict__ x2) {
    int i = blockIdx.x * blockDim.x + threadIdx.x;
    int stride = gridDim.x * blockDim.x;
    for (int j = i; j < N_NODES * ELLW; j += stride) g_ell[j] = SENT;
    for (int j = i; j < N_NODES; j += stride) g_cnt[j] = 0;
    for (int j = i; j < N_NODES * 16; j += stride) {
        float2 v = x2[j];
        g_x16[j] = __floats2half2_rn(v.x, v.y);
    }
    if (i < 16) g_x16[N_NODES * 16 + i] = __floats2half2_rn(0.f, 0.f);
    if (i < 32) g_h016[N_NODES * 32 + i] = __floats2half2_rn(0.f, 0.f);
}

// Launch 2: ELL fill (atomic cursor per destination node)
__global__ void k_ellfill(const int* __restrict__ ei, int E) {
    int e = blockIdx.x * blockDim.x + threadIdx.x;
    if (e >= E) return;
    int src = ei[e];
    int dst = ei[E + e];
    int pos = atomicAdd(g_cnt + dst, 1);
    if (pos < ELLW) g_ell[dst * ELLW + pos] = src;
}

// ---------------------------------------------------------------------------
// Launch 3: Layer 0. Block = 32 nodes, 256 threads (8 warps).
// Phase A: sentinel-padded (to 8) gather, HADD2-paired -> fp16 act.
// Phase B: wmma GEMM 32x64x64.  Phase C: bias+normalize+relu -> g_h016.
#define L0_ALD 72     // act ld (halves)
#define L0_CLD 68     // C ld (floats)
__global__ void __launch_bounds__(256, 6) k_layer0(
        const float* __restrict__ Wl0,
        const float* __restrict__ b0,
        const float* __restrict__ Wr0) {
    __shared__ alignas(16) char uAC[NB * L0_CLD * 4];   // act fp16 then C fp32
    __shared__ alignas(16) __half sW[64 * L0_ALD];
    __shared__ float sb[HID];

    __half* Act = reinterpret_cast<__half*>(uAC);
    float*  Cm  = reinterpret_cast<float*>(uAC);

    int tid  = threadIdx.x;
    int warp = tid >> 5;
    int lane = tid & 31;

    for (int j = tid; j < 64 * HID; j += 256) {
        int kk = j >> 6, o = j & 63;
        float w = (kk < 32) ? Wl0[kk * HID + o] : Wr0[(kk - 32) * HID + o];
        sW[kk * L0_ALD + o] = __float2half(w);
    }
    if (tid < HID) sb[tid] = b0[tid];
    __syncthreads();

    // ---- Phase A: gather (4 rounds, warp per node) ----
    int g = lane >> 4;      // half-warp id (0,1)
    int c = lane & 15;      // half2 index within 32-ch row
#pragma unroll 1
    for (int r = 0; r < 4; r++) {
        int n = r * 8 + warp;
        int node = blockIdx.x * NB + n;
        if (node < N_NODES) {
            int deg  = g_cnt[node];
            int degP = min((deg + 7) & ~7, ELLW);   // sentinel-padded to 8
            int row  = node * ELLW;
            float ax = 0.f, ay = 0.f;
            for (int base = 0; base < degP; base += 32) {
                int nb = g_ell[row + base + lane];   // sentinel beyond deg
                int rem = degP - base;               // multiple of 8, warp-uniform
#pragma unroll
                for (int i = 0; i < 32; i += 8) {    // 8 neighbors per step (4 per half-warp)
                    int s0 = __shfl_sync(FULL, nb, i + g);
                    int s1 = __shfl_sync(FULL, nb, i + 2 + g);
                    int s2 = __shfl_sync(FULL, nb, i + 4 + g);
                    int s3 = __shfl_sync(FULL, nb, i + 6 + g);
                    __half2 h0p = __hadd2(g_x16[s0 * 16 + c], g_x16[s1 * 16 + c]);
                    __half2 h1p = __hadd2(g_x16[s2 * 16 + c], g_x16[s3 * 16 + c]);
                    float2 f0 = __half22float2(h0p);
                    float2 f1 = __half22float2(h1p);
                    ax += f0.x + f1.x;
                    ay += f0.y + f1.y;
                    if (i + 8 >= rem) break;         // warp-uniform
                }
            }
            ax += __shfl_xor_sync(FULL, ax, 16);
            ay += __shfl_xor_sync(FULL, ay, 16);
            float ic = 1.0f / fmaxf((float)deg, 1.0f);
            __half2* arow = reinterpret_cast<__half2*>(Act + n * L0_ALD);
            if (lane < 16) arow[c] = __floats2half2_rn(ax * ic, ay * ic);   // mean ch{2c,2c+1}
            else           arow[16 + c] = g_x16[node * 16 + c];             // self
        }
    }
    __syncthreads();

    // ---- Phase B: wmma GEMM 32x64x64 (8 tiles, 1 per warp) ----
    {
        int mi = warp & 1;          // row tile 0..1
        int nj = warp >> 1;         // col tile 0..3
        wmma::fragment<wmma::accumulator, 16, 16, 16, float> cf;
        wmma::fill_fragment(cf, 0.0f);
#pragma unroll
        for (int k = 0; k < 4; k++) {
            wmma::fragment<wmma::matrix_a, 16, 16, 16, __half, wmma::row_major> a;
            wmma::fragment<wmma::matrix_b, 16, 16, 16, __half, wmma::row_major> bf;
            wmma::load_matrix_sync(a, Act + (mi * 16) * L0_ALD + k * 16, L0_ALD);
            wmma::load_matrix_sync(bf, sW + (k * 16) * L0_ALD + nj * 16, L0_ALD);
            wmma::mma_sync(cf, a, bf, cf);
        }
        __syncthreads();   // done reading Act before overwriting as C
        wmma::store_matrix_sync(Cm + (mi * 16) * L0_CLD + nj * 16, cf, L0_CLD, wmma::mem_row_major);
    }
    __syncthreads();

    // ---- Phase C: bias + normalize + relu -> g_h016 ----
#pragma unroll 1
    for (int r = 0; r < 4; r++) {
        int n = r * 8 + warp;
        int node = blockIdx.x * NB + n;
        if (node >= N_NODES) continue;
        float a0 = Cm[n * L0_CLD + lane]      + sb[lane];
        float a1 = Cm[n * L0_CLD + lane + 32] + sb[lane + 32];
        float ss = a0 * a0 + a1 * a1;
#pragma unroll
        for (int off = 16; off > 0; off >>= 1)
            ss += __shfl_xor_sync(FULL, ss, off);
        float inv = 1.0f / fmaxf(sqrtf(ss), 1e-12f);
        float o0 = fmaxf(a0 * inv, 0.0f);
        float o1 = fmaxf(a1 * inv, 0.0f);
        int src_lo = (2 * lane) & 31, src_hi = (2 * lane + 1) & 31;
        float lo0 = __shfl_sync(FULL, o0, src_lo);
        float lo1 = __shfl_sync(FULL, o1, src_lo);
        float hi0 = __shfl_sync(FULL, o0, src_hi);
        float hi1 = __shfl_sync(FULL, o1, src_hi);
        float lo = (lane < 16) ? lo0 : lo1;
        float hi = (lane < 16) ? hi0 : hi1;
        g_h016[node * 32 + lane] = __floats2half2_rn(lo, hi);
    }
}

// ---------------------------------------------------------------------------
// Launch 4: Layer 1 + classifier. Block = 32 nodes, 256 threads.
// Phase A: sentinel-padded (to 8) gather, HADD2-paired.
// Phase B: wmma 32x64x128. Phase C: bias+normalize -> h1 fp16.
// Phase D: wmma 32x32x64. Phase E: bias+relu+dot -> out.
#define L1_ALD 136    // act ld (halves)
#define L1_WLD 72     // weight ld
#define L1_CLD 68     // C ld (floats)
#define H1_LD  72     // h1 ld (halves)
#define C2_LD  36     // C2 ld (floats)
#define WC_LD  40     // Wc1 ld (halves)
__global__ void __launch_bounds__(256, 5) k_layer1(
        const float* __restrict__ Wl1,
        const float* __restrict__ b1,
        const float* __restrict__ Wr1,
        const float* __restrict__ Wc1,
        const float* __restrict__ bc1,
        const float* __restrict__ Wc2,
        const float* __restrict__ bc2,
        float* __restrict__ out) {
    __shared__ alignas(16) char uAC[NB * L1_ALD * 2];          // act fp16 == C fp32 (8704B)
    __shared__ alignas(16) char uW[128 * L1_WLD * 2];          // W fp16 -> H1 fp16 | C2 fp32
    __shared__ alignas(16) __half sWc1h[64 * WC_LD];
    __shared__ float sb[HID];
    __shared__ float sbc1[32];
    __shared__ float sWc2s[32];

    __half* Act = reinterpret_cast<__half*>(uAC);
    float*  Cm  = reinterpret_cast<float*>(uAC);
    __half* W   = reinterpret_cast<__half*>(uW);
    __half* H1  = reinterpret_cast<__half*>(uW);               // 32*72*2 = 4608B
    float*  C2  = reinterpret_cast<float*>(uW + 4608);         // 32*36*4 = 4608B

    int tid  = threadIdx.x;
    int warp = tid >> 5;
    int lane = tid & 31;

    for (int j = tid; j < 128 * HID; j += 256) {
        int kk = j >> 6, o = j & 63;
        float w = (kk < 64) ? Wl1[kk * HID + o] : Wr1[(kk - 64) * HID + o];
        W[kk * L1_WLD + o] = __float2half(w);
    }
    for (int j = tid; j < 64 * 32; j += 256) {
        int kk = j >> 5, o = j & 31;
        sWc1h[kk * WC_LD + o] = __float2half(Wc1[kk * 32 + o]);
    }
    if (tid < HID) sb[tid] = b1[tid];
    if (tid < 32) { sbc1[tid] = bc1[tid]; sWc2s[tid] = Wc2[tid]; }
    __syncthreads();

    // ---- Phase A: gather (4 rounds, warp per node) ----
#pragma unroll 1
    for (int r = 0; r < 4; r++) {
        int n = r * 8 + warp;
        int node = blockIdx.x * NB + n;
        if (node < N_NODES) {
            int deg  = g_cnt[node];
            int degP = min((deg + 7) & ~7, ELLW);   // sentinel-padded to 8
            int row  = node * ELLW;
            float ax = 0.f, ay = 0.f;   // ch {2*lane, 2*lane+1}
            for (int base = 0; base < degP; base += 32) {
                int nb = g_ell[row + base + lane];   // sentinel beyond deg
                int rem = degP - base;               // multiple of 8, warp-uniform
#pragma unroll
                for (int i = 0; i < 32; i += 8) {    // 8 neighbors per step
                    int s0 = __shfl_sync(FULL, nb, i);
                    int s1 = __shfl_sync(FULL, nb, i + 1);
                    int s2 = __shfl_sync(FULL, nb, i + 2);
                    int s3 = __shfl_sync(FULL, nb, i + 3);
                    int s4 = __shfl_sync(FULL, nb, i + 4);
                    int s5 = __shfl_sync(FULL, nb, i + 5);
                    int s6 = __shfl_sync(FULL, nb, i + 6);
                    int s7 = __shfl_sync(FULL, nb, i + 7);
                    __half2 p0 = __hadd2(g_h016[s0 * 32 + lane], g_h016[s1 * 32 + lane]);
                    __half2 p1 = __hadd2(g_h016[s2 * 32 + lane], g_h016[s3 * 32 + lane]);
                    __half2 p2 = __hadd2(g_h016[s4 * 32 + lane], g_h016[s5 * 32 + lane]);
                    __half2 p3 = __hadd2(g_h016[s6 * 32 + lane], g_h016[s7 * 32 + lane]);
                    float2 f0 = __half22float2(p0);
                    float2 f1 = __half22float2(p1);
                    float2 f2 = __half22float2(p2);
                    float2 f3 = __half22float2(p3);
                    ax += (f0.x + f1.x) + (f2.x + f3.x);
                    ay += (f0.y + f1.y) + (f2.y + f3.y);
                    if (i + 8 >= rem) break;         // warp-uniform
                }
            }
            float ic = 1.0f / fmaxf((float)deg, 1.0f);
            __half2* arow = reinterpret_cast<__half2*>(Act + n * L1_ALD);
            arow[lane]      = __floats2half2_rn(ax * ic, ay * ic);   // mean ch{2l,2l+1}
            arow[32 + lane] = g_h016[node * 32 + lane];              // self
        }
    }
    __syncthreads();

    // ---- Phase B: wmma GEMM 32x64x128 (8 tiles, 1 per warp) ----
    {
        int mi = warp & 1;
        int nj = warp >> 1;   // 0..3
        wmma::fragment<wmma::accumulator, 16, 16, 16, float> cf;
        wmma::fill_fragment(cf, 0.0f);
#pragma unroll
        for (int k = 0; k < 8; k++) {
            wmma::fragment<wmma::matrix_a, 16, 16, 16, __half, wmma::row_major> a;
            wmma::fragment<wmma::matrix_b, 16, 16, 16, __half, wmma::row_major> bf;
            wmma::load_matrix_sync(a, Act + (mi * 16) * L1_ALD + k * 16, L1_ALD);
            wmma::load_matrix_sync(bf, W + (k * 16) * L1_WLD + nj * 16, L1_WLD);
            wmma::mma_sync(cf, a, bf, cf);
        }
        __syncthreads();   // done reading Act before overwriting as C
        wmma::store_matrix_sync(Cm + (mi * 16) * L1_CLD + nj * 16, cf, L1_CLD, wmma::mem_row_major);
    }
    __syncthreads();

    // ---- Phase C: bias + normalize -> H1 fp16 (overwrites W region) ----
#pragma unroll 1
    for (int r = 0; r < 4; r++) {
        int n = r * 8 + warp;
        float a0 = Cm[n * L1_CLD + lane]      + sb[lane];
        float a1 = Cm[n * L1_CLD + lane + 32] + sb[lane + 32];
        float ss = a0 * a0 + a1 * a1;
#pragma unroll
        for (int off = 16; off > 0; off >>= 1)
            ss += __shfl_xor_sync(FULL, ss, off);
        float inv = 1.0f / fmaxf(sqrtf(ss), 1e-12f);
        H1[n * H1_LD + lane]      = __float2half(a0 * inv);
        H1[n * H1_LD + lane + 32] = __float2half(a1 * inv);
    }
    __syncthreads();

    // ---- Phase D: wmma GEMM 32x32x64 (4 tiles, warps 0-3) ----
    if (warp < 4) {
        int mi = warp & 1;
        int nj = warp >> 1;   // 0..1
        wmma::fragment<wmma::accumulator, 16, 16, 16, float> cf;
        wmma::fill_fragment(cf, 0.0f);
#pragma unroll
        for (int k = 0; k < 4; k++) {
            wmma::fragment<wmma::matrix_a, 16, 16, 16, __half, wmma::row_major> a;
            wmma::fragment<wmma::matrix_b, 16, 16, 16, __half, wmma::row_major> bf;
            wmma::load_matrix_sync(a, H1 + (mi * 16) * H1_LD + k * 16, H1_LD);
            wmma::load_matrix_sync(bf, sWc1h + (k * 16) * WC_LD + nj * 16, WC_LD);
            wmma::mma_sync(cf, a, bf, cf);
        }
        wmma::store_matrix_sync(C2 + (mi * 16) * C2_LD + nj * 16, cf, C2_LD, wmma::mem_row_major);
    }
    __syncthreads();

    // ---- Phase E: bias + relu + dot(Wc2) -> out ----
#pragma unroll 1
    for (int r = 0; r < 4; r++) {
        int n = r * 8 + warp;
        int node = blockIdx.x * NB + n;
        if (node >= N_NODES) continue;
        float v = C2[n * C2_LD + lane] + sbc1[lane];
        v = fmaxf(v, 0.0f);
        float p = v * sWc2s[lane];
#pragma unroll
        for (int off = 16; off > 0; off >>= 1)
            p += __shfl_xor_sync(FULL, p, off);
        if (lane == 0) out[node] = p + bc2[0];
    }
}

// ---------------------------------------------------------------------------
extern "C" void kernel_launch(void* const* d_in, const int* in_sizes, int n_in,
                              void* d_out, int out_size) {
    const float* x    = (const float*)d_in[0];
    const int*   ei   = (const int*)d_in[1];     // int32 edge index
    const float* Wl0  = (const float*)d_in[2];
    const float* b0   = (const float*)d_in[3];
    const float* Wr0  = (const float*)d_in[4];
    const float* Wl1  = (const float*)d_in[5];
    const float* b1   = (const float*)d_in[6];
    const float* Wr1  = (const float*)d_in[7];
    const float* Wc1  = (const float*)d_in[8];
    const float* bc1  = (const float*)d_in[9];
    const float* Wc2  = (const float*)d_in[10];
    const float* bc2  = (const float*)d_in[11];
    float* out = (float*)d_out;

    int E = in_sizes[1] / 2;   // 1,600,000
    int nblk = (N_NODES + NB - 1) / NB;

    k_prep<<<1024, 256>>>((const float2*)x);
    k_ellfill<<<(E + 255) / 256, 256>>>(ei, E);
    k_layer0<<<nblk, 256>>>(Wl0, b0, Wr0);
    k_layer1<<<nblk, 256>>>(Wl1, b1, Wr1, Wc1, bc1, Wc2, bc2, out);
}